// round 1
// baseline (speedup 1.0000x reference)
#include <cuda_runtime.h>
#include <cstdint>

#define B_ 4
#define T_ 2048
#define C_ 1024
#define H_ 16
#define D_ 64

// Scratch (static __device__ globals: allocation-free per harness rules)
__device__ float g_qkv[(size_t)3 * B_ * H_ * T_ * D_];   // [which][b][h][t][d]
__device__ float g_att[(size_t)B_ * T_ * C_];            // [b][t][h*D+d]

// ---------------------------------------------------------------------------
// SGEMM: out[M,N] = A[M,K] @ W[K,N] + bias[N]
// MODE 0: A = x, scatter-write into g_qkv as [3][B][H][T][D]
// MODE 1: A = g_att, plain row-major write to out
// BM=BN=128, BK=16, 256 threads, 8x8 per thread.
// ---------------------------------------------------------------------------
template <int MODE>
__global__ __launch_bounds__(256) void sgemm_kernel(
    const float* __restrict__ A, const float* __restrict__ W,
    const float* __restrict__ bias, float* __restrict__ out,
    int M, int N, int K)
{
    __shared__ float AsT[16][132];   // transposed A tile, padded (2-way max)
    __shared__ float Bs[16][128];

    const int tid = threadIdx.x;
    const int ty = tid >> 4;         // 0..15
    const int tx = tid & 15;         // 0..15
    const int bm = blockIdx.y, bn = blockIdx.x;

    const float* Aeff = (MODE == 1) ? g_att : A;
    const float* Ap = Aeff + (size_t)bm * 128 * K;
    const float* Wp = W + (size_t)bn * 128;

    float acc[8][8] = {};

    for (int k0 = 0; k0 < K; k0 += 16) {
#pragma unroll
        for (int it = 0; it < 2; ++it) {
            int f = tid + it * 256;          // 0..511
            int r = f >> 2, c4 = f & 3;      // A: 128 rows x 4 float4-cols
            float4 av = *(const float4*)(Ap + (size_t)r * K + k0 + c4 * 4);
            AsT[c4 * 4 + 0][r] = av.x;
            AsT[c4 * 4 + 1][r] = av.y;
            AsT[c4 * 4 + 2][r] = av.z;
            AsT[c4 * 4 + 3][r] = av.w;
            int rb = f >> 5, cb = f & 31;    // B: 16 rows x 32 float4-cols
            float4 wv = *(const float4*)(Wp + (size_t)(k0 + rb) * N + cb * 4);
            *(float4*)&Bs[rb][cb * 4] = wv;
        }
        __syncthreads();
#pragma unroll
        for (int kk = 0; kk < 16; ++kk) {
            float a[8], b[8];
            *(float4*)&a[0] = *(const float4*)&AsT[kk][ty * 8];
            *(float4*)&a[4] = *(const float4*)&AsT[kk][ty * 8 + 4];
            *(float4*)&b[0] = *(const float4*)&Bs[kk][tx * 8];
            *(float4*)&b[4] = *(const float4*)&Bs[kk][tx * 8 + 4];
#pragma unroll
            for (int i = 0; i < 8; ++i)
#pragma unroll
                for (int j = 0; j < 8; ++j)
                    acc[i][j] = fmaf(a[i], b[j], acc[i][j]);
        }
        __syncthreads();
    }

    // Epilogue
    const int n0 = bn * 128 + tx * 8;
    float bv[8];
    *(float4*)&bv[0] = *(const float4*)&bias[n0];
    *(float4*)&bv[4] = *(const float4*)&bias[n0 + 4];

#pragma unroll
    for (int i = 0; i < 8; ++i) {
        int m = bm * 128 + ty * 8 + i;
        float vv[8];
#pragma unroll
        for (int j = 0; j < 8; ++j) vv[j] = acc[i][j] + bv[j];
        if (MODE == 0) {
            // n0..n0+7 stays within one 64-block (8-aligned), so which/h/d0 constant
            int which = n0 >> 10;
            int h = (n0 & 1023) >> 6;
            int d0 = n0 & 63;
            int bb = m >> 11;        // m / T
            int t = m & 2047;        // m % T
            float* dst = &g_qkv[(((((size_t)which * B_ + bb) * H_ + h) * T_ + t) * D_) + d0];
            *(float4*)(dst + 0) = *(float4*)&vv[0];
            *(float4*)(dst + 4) = *(float4*)&vv[4];
        } else {
            float* dst = out + (size_t)m * N + n0;
            *(float4*)(dst + 0) = *(float4*)&vv[0];
            *(float4*)(dst + 4) = *(float4*)&vv[4];
        }
    }
}

// ---------------------------------------------------------------------------
// Flash attention, causal. BQ=64, BK=64, D=64, 256 threads (16x16), 4x4/thread.
// Q tile resident; K tile XOR-swizzled (conflict-free transpose-free access);
// P tile aliases the K tile region (48 KB static smem total -> 4 CTAs/SM).
// Reads g_qkv, writes g_att in [B,T,H*D] layout for the proj GEMM.
// ---------------------------------------------------------------------------
__global__ __launch_bounds__(256) void attn_kernel()
{
    __shared__ float Qs[64][64];     // [q][d]
    __shared__ float KP[64 * 64];    // Ks (swizzled [k][d]) then Ps ([q][k])
    __shared__ float Vs[64][64];     // [k][d]

    const int tid = threadIdx.x;
    const int ty = tid >> 4;         // 0..15 -> 4 q-rows
    const int tx = tid & 15;         // 0..15 -> 4 k-cols / d-cols
    const int qb = blockIdx.x;
    const int bh = blockIdx.y;
    const int q0 = qb * 64;
    const int ty4 = ty * 4;

    const size_t plane = (size_t)B_ * H_ * T_ * D_;
    const float* qbase = g_qkv + ((size_t)bh * T_ + q0) * D_;
    const float* kbase = g_qkv + plane + (size_t)bh * T_ * D_;
    const float* vbase = kbase + plane;

    // Load Q tile (64x64 = 1024 float4)
#pragma unroll
    for (int it = 0; it < 4; ++it) {
        int f = tid + it * 256;
        ((float4*)Qs)[f] = ((const float4*)qbase)[f];
    }

    float rO[4][4] = {};
    float mrow[4], lrow[4];
#pragma unroll
    for (int i = 0; i < 4; ++i) { mrow[i] = -1e30f; lrow[i] = 0.f; }

    for (int kb = 0; kb <= qb; ++kb) {
        const float4* ksrc = (const float4*)(kbase + (size_t)kb * 64 * D_);
        const float4* vsrc = (const float4*)(vbase + (size_t)kb * 64 * D_);
#pragma unroll
        for (int it = 0; it < 4; ++it) {
            int f = tid + it * 256;
            int r = f >> 4, c4 = f & 15;
            float4 kv = ksrc[f];
            int p4 = (c4 ^ (r >> 2)) & 15;               // XOR swizzle
            *(float4*)&KP[r * 64 + p4 * 4] = kv;
            ((float4*)Vs)[f] = vsrc[f];
        }
        __syncthreads();

        // S = Q @ K^T  (4x4 per thread), d unrolled by 4 for float4 LDS
        float s[4][4] = {};
#pragma unroll 4
        for (int d4 = 0; d4 < 16; ++d4) {
            float av[4][4], bm[4][4];
            int p4 = (d4 ^ tx) & 15;
#pragma unroll
            for (int i = 0; i < 4; ++i)
                *(float4*)&av[i][0] = *(const float4*)&Qs[ty4 + i][d4 << 2];
#pragma unroll
            for (int j = 0; j < 4; ++j)
                *(float4*)&bm[j][0] = *(const float4*)&KP[(tx * 4 + j) * 64 + p4 * 4];
#pragma unroll
            for (int i = 0; i < 4; ++i)
#pragma unroll
                for (int j = 0; j < 4; ++j)
#pragma unroll
                    for (int u = 0; u < 4; ++u)
                        s[i][j] = fmaf(av[i][u], bm[j][u], s[i][j]);
        }

        // scale + causal mask (only the diagonal tile needs masking)
        const bool diag = (kb == qb);
#pragma unroll
        for (int i = 0; i < 4; ++i)
#pragma unroll
            for (int j = 0; j < 4; ++j) {
                float v = s[i][j] * 0.125f;
                if (diag && (tx * 4 + j) > (ty4 + i)) v = -1e30f;
                s[i][j] = v;
            }

        // online softmax (rows split across 16 tx threads; lane = ((ty&1)<<4)|tx)
#pragma unroll
        for (int i = 0; i < 4; ++i) {
            float mt = fmaxf(fmaxf(s[i][0], s[i][1]), fmaxf(s[i][2], s[i][3]));
#pragma unroll
            for (int w = 8; w >= 1; w >>= 1)
                mt = fmaxf(mt, __shfl_xor_sync(0xffffffffu, mt, w));
            float mn = fmaxf(mrow[i], mt);
            float alpha = __expf(mrow[i] - mn);
            mrow[i] = mn;
            float rs = 0.f;
#pragma unroll
            for (int j = 0; j < 4; ++j) {
                s[i][j] = __expf(s[i][j] - mn);
                rs += s[i][j];
            }
#pragma unroll
            for (int w = 8; w >= 1; w >>= 1)
                rs += __shfl_xor_sync(0xffffffffu, rs, w);
            lrow[i] = lrow[i] * alpha + rs;
#pragma unroll
            for (int j = 0; j < 4; ++j) rO[i][j] *= alpha;
        }

        __syncthreads();     // everyone done reading Ks
        // write P tile (plain [q][k] layout over the K region)
#pragma unroll
        for (int i = 0; i < 4; ++i)
#pragma unroll
            for (int j = 0; j < 4; ++j)
                KP[(ty4 + i) * 64 + tx * 4 + j] = s[i][j];
        __syncthreads();

        // O += P @ V  (k unrolled by 4 for float4 LDS)
#pragma unroll 4
        for (int c4 = 0; c4 < 16; ++c4) {
            float av[4][4], bm[4][4];
#pragma unroll
            for (int i = 0; i < 4; ++i)
                *(float4*)&av[i][0] = *(const float4*)&KP[(ty4 + i) * 64 + (c4 << 2)];
#pragma unroll
            for (int u = 0; u < 4; ++u)
                *(float4*)&bm[u][0] = *(const float4*)&Vs[(c4 << 2) + u][tx * 4];
#pragma unroll
            for (int i = 0; i < 4; ++i)
#pragma unroll
                for (int u = 0; u < 4; ++u)
#pragma unroll
                    for (int j = 0; j < 4; ++j)
                        rO[i][j] = fmaf(av[i][u], bm[u][j], rO[i][j]);
        }
        __syncthreads();
    }

    // normalize + write to g_att in [B, T, H*D] layout
    const int b = bh >> 4, h = bh & 15;
    float* obase = g_att + (size_t)(b * T_ + q0) * C_ + h * D_;
#pragma unroll
    for (int i = 0; i < 4; ++i) {
        float inv = 1.0f / lrow[i];
        float4 o;
        o.x = rO[i][0] * inv; o.y = rO[i][1] * inv;
        o.z = rO[i][2] * inv; o.w = rO[i][3] * inv;
        *(float4*)(obase + (size_t)(ty4 + i) * C_ + tx * 4) = o;
    }
}

// ---------------------------------------------------------------------------
extern "C" void kernel_launch(void* const* d_in, const int* in_sizes, int n_in,
                              void* d_out, int out_size)
{
    const float* x      = (const float*)d_in[0];
    const float* w_qkv  = (const float*)d_in[1];
    const float* b_qkv  = (const float*)d_in[2];
    const float* w_proj = (const float*)d_in[3];
    const float* b_proj = (const float*)d_in[4];
    float* out = (float*)d_out;

    // 1) QKV projection: [8192,1024] @ [1024,3072] -> scattered q/k/v
    sgemm_kernel<0><<<dim3((3 * C_) / 128, (B_ * T_) / 128), 256>>>(
        x, w_qkv, b_qkv, nullptr, B_ * T_, 3 * C_, C_);

    // 2) causal flash attention -> g_att [B,T,C]
    attn_kernel<<<dim3(T_ / 64, B_ * H_), 256>>>();

    // 3) output projection: [8192,1024] @ [1024,1024] -> d_out
    sgemm_kernel<1><<<dim3(C_ / 128, (B_ * T_) / 128), 256>>>(
        nullptr, w_proj, b_proj, out, B_ * T_, C_, C_);
}

// round 5
// speedup vs baseline: 1.6182x; 1.6182x over previous
#include <cuda_runtime.h>
#include <cuda_bf16.h>
#include <cstdint>

#define B_ 4
#define T_ 2048
#define C_ 1024
#define H_ 16
#define D_ 64

// Scratch (static __device__ globals: allocation-free per harness rules)
__device__ float g_qkv[(size_t)3 * B_ * H_ * T_ * D_];   // [which][b][h][t][d]
__device__ float g_att[(size_t)B_ * T_ * C_];            // [b][t][h*D+d]

// ---------------------------------------------------------------------------
// Helpers (compute_103-safe: only ldmatrix + mma.sync, no tcgen05)
// ---------------------------------------------------------------------------
static __device__ __forceinline__ uint32_t smem_u32(const void* p) {
    uint32_t a;
    asm("{ .reg .u64 t; cvta.to.shared.u64 t, %1; cvt.u32.u64 %0, t; }"
        : "=r"(a) : "l"(p));
    return a;
}

#define LDM_X4(r, addr) \
    asm volatile("ldmatrix.sync.aligned.m8n8.x4.shared.b16 {%0,%1,%2,%3}, [%4];" \
        : "=r"((r)[0]), "=r"((r)[1]), "=r"((r)[2]), "=r"((r)[3]) : "r"(addr))

#define LDM_X4T(r, addr) \
    asm volatile("ldmatrix.sync.aligned.m8n8.x4.trans.shared.b16 {%0,%1,%2,%3}, [%4];" \
        : "=r"((r)[0]), "=r"((r)[1]), "=r"((r)[2]), "=r"((r)[3]) : "r"(addr))

#define MMA_BF16(d, a, b0, b1) \
    asm volatile("mma.sync.aligned.m16n8k16.row.col.f32.bf16.bf16.f32 " \
        "{%0,%1,%2,%3}, {%4,%5,%6,%7}, {%8,%9}, {%0,%1,%2,%3};" \
        : "+f"((d)[0]), "+f"((d)[1]), "+f"((d)[2]), "+f"((d)[3]) \
        : "r"((a)[0]), "r"((a)[1]), "r"((a)[2]), "r"((a)[3]), "r"(b0), "r"(b1))

// fp32 -> (hi, lo) bf16 split
static __device__ __forceinline__ void split2(float v, __nv_bfloat16& h, __nv_bfloat16& l) {
    h = __float2bfloat16_rn(v);
    l = __float2bfloat16_rn(v - __bfloat162float(h));
}
static __device__ __forceinline__ uint32_t pack2(__nv_bfloat16 a, __nv_bfloat16 b) {
    __nv_bfloat162 t; t.x = a; t.y = b;
    uint32_t u; __builtin_memcpy(&u, &t, 4);
    return u;
}

// Padded strides (elements): A rows 40 bf16 (80B), B rows 136 bf16 (272B).
// 80*i mod 128 and 272*i mod 128 both cycle through 8 distinct 16B banks ->
// conflict-free ldmatrix.
#define A_PITCH 40
#define B_PITCH 136

// ---------------------------------------------------------------------------
// HMMA GEMM with bf16x3 split: out[M,N] = A[M,K] @ W[K,N] + bias
// MODE 0: A = x, scatter into g_qkv[3][B][H][T][D].  MODE 1: A = g_att -> out.
// BM=BN=128, BK=32, 256 threads (8 warps = 4m x 2n), warp tile 32x64.
// ---------------------------------------------------------------------------
template <int MODE>
__global__ __launch_bounds__(256, 2) void gemm_mma(
    const float* __restrict__ A, const float* __restrict__ W,
    const float* __restrict__ bias, float* __restrict__ out,
    int M, int N, int K)
{
    __shared__ __align__(16) __nv_bfloat16 AsH[128 * A_PITCH];
    __shared__ __align__(16) __nv_bfloat16 AsL[128 * A_PITCH];
    __shared__ __align__(16) __nv_bfloat16 BsH[32 * B_PITCH];
    __shared__ __align__(16) __nv_bfloat16 BsL[32 * B_PITCH];

    const int tid = threadIdx.x;
    const int wid = tid >> 5;
    const int lane = tid & 31;
    const int wm = wid >> 1;          // 0..3
    const int wn = wid & 1;           // 0..1
    const int bm = blockIdx.y, bn = blockIdx.x;

    const uint32_t sAH = smem_u32(AsH), sAL = smem_u32(AsL);
    const uint32_t sBH = smem_u32(BsH), sBL = smem_u32(BsL);

    const float* Aeff = (MODE == 1) ? g_att : A;
    const float* Ap = Aeff + (size_t)bm * 128 * K;
    const float* Wp = W + (size_t)bn * 128;

    float acc[2][8][4] = {};

    // precomputed ldmatrix lane addresses (byte offsets into the tiles)
    const int l15 = lane & 15;
    const int lhi = lane >> 4;                 // 0/1
    const uint32_t a_off0 = (uint32_t)(wm * 32 + l15) * (A_PITCH * 2) + (lhi << 4);
    const uint32_t b_off0 = (uint32_t)l15 * (B_PITCH * 2) + ((wn * 64 + (lhi << 3)) << 1);

    for (int kt = 0; kt < K / 32; ++kt) {
        // ---- load + split: A 128x32, W 32x128 (fp32 -> bf16 hi/lo)
#pragma unroll
        for (int i = 0; i < 4; ++i) {
            int f = tid + i * 256;             // 0..1023
            {   // A: 128 rows x 8 float4
                int r = f >> 3, c4 = f & 7;
                float4 v = *(const float4*)(Ap + (size_t)r * K + kt * 32 + c4 * 4);
                __nv_bfloat16 h0, h1, h2, h3, l0, l1, l2, l3;
                split2(v.x, h0, l0); split2(v.y, h1, l1);
                split2(v.z, h2, l2); split2(v.w, h3, l3);
                int e = r * A_PITCH + c4 * 4;
                *(uint2*)&AsH[e] = make_uint2(pack2(h0, h1), pack2(h2, h3));
                *(uint2*)&AsL[e] = make_uint2(pack2(l0, l1), pack2(l2, l3));
            }
            {   // W: 32 rows x 32 float4
                int r = f >> 5, c4 = f & 31;
                float4 v = *(const float4*)(Wp + (size_t)(kt * 32 + r) * N + c4 * 4);
                __nv_bfloat16 h0, h1, h2, h3, l0, l1, l2, l3;
                split2(v.x, h0, l0); split2(v.y, h1, l1);
                split2(v.z, h2, l2); split2(v.w, h3, l3);
                int e = r * B_PITCH + c4 * 4;
                *(uint2*)&BsH[e] = make_uint2(pack2(h0, h1), pack2(h2, h3));
                *(uint2*)&BsL[e] = make_uint2(pack2(l0, l1), pack2(l2, l3));
            }
        }
        __syncthreads();

        // ---- MMA: 2 k16 steps, bf16x3 (Ah*Bh + Al*Bh + Ah*Bl)
#pragma unroll
        for (int ks = 0; ks < 2; ++ks) {
            uint32_t ah[2][4], al[2][4], bfr[4][4];
#pragma unroll
            for (int mf = 0; mf < 2; ++mf) {
                uint32_t ao = a_off0 + (uint32_t)mf * 16 * (A_PITCH * 2) + ks * 32;
                LDM_X4(ah[mf], sAH + ao);
                LDM_X4(al[mf], sAL + ao);
            }
            const uint32_t bks = b_off0 + (uint32_t)ks * 16 * (B_PITCH * 2);
#pragma unroll
            for (int ng = 0; ng < 4; ++ng)
                LDM_X4T(bfr[ng], sBH + bks + ng * 32);
#pragma unroll
            for (int mf = 0; mf < 2; ++mf)
#pragma unroll
                for (int nf = 0; nf < 8; ++nf)
                    MMA_BF16(acc[mf][nf], ah[mf], bfr[nf >> 1][(nf & 1) * 2],
                             bfr[nf >> 1][(nf & 1) * 2 + 1]);
#pragma unroll
            for (int mf = 0; mf < 2; ++mf)
#pragma unroll
                for (int nf = 0; nf < 8; ++nf)
                    MMA_BF16(acc[mf][nf], al[mf], bfr[nf >> 1][(nf & 1) * 2],
                             bfr[nf >> 1][(nf & 1) * 2 + 1]);
#pragma unroll
            for (int ng = 0; ng < 4; ++ng)
                LDM_X4T(bfr[ng], sBL + bks + ng * 32);
#pragma unroll
            for (int mf = 0; mf < 2; ++mf)
#pragma unroll
                for (int nf = 0; nf < 8; ++nf)
                    MMA_BF16(acc[mf][nf], ah[mf], bfr[nf >> 1][(nf & 1) * 2],
                             bfr[nf >> 1][(nf & 1) * 2 + 1]);
        }
        __syncthreads();
    }

    // ---- epilogue: d-frag rows (tr, tr+8), cols (tc, tc+1)
    const int tr = lane >> 2;
    const int tc = (lane & 3) * 2;
#pragma unroll
    for (int mf = 0; mf < 2; ++mf) {
        const int m0 = bm * 128 + wm * 32 + mf * 16 + tr;
#pragma unroll
        for (int nf = 0; nf < 8; ++nf) {
            const int n0 = bn * 128 + wn * 64 + nf * 8 + tc;
            const float bx = __ldg(&bias[n0]);
            const float by = __ldg(&bias[n0 + 1]);
            float2 v0 = make_float2(acc[mf][nf][0] + bx, acc[mf][nf][1] + by);
            float2 v1 = make_float2(acc[mf][nf][2] + bx, acc[mf][nf][3] + by);
            if (MODE == 0) {
                const int which = n0 >> 10;
                const int h = (n0 & 1023) >> 6;
                const int d0 = n0 & 63;
                {
                    int bb = m0 >> 11, t = m0 & 2047;
                    *(float2*)&g_qkv[(((((size_t)which * B_ + bb) * H_ + h) * T_ + t) * D_) + d0] = v0;
                }
                {
                    int m1 = m0 + 8;
                    int bb = m1 >> 11, t = m1 & 2047;
                    *(float2*)&g_qkv[(((((size_t)which * B_ + bb) * H_ + h) * T_ + t) * D_) + d0] = v1;
                }
            } else {
                *(float2*)(out + (size_t)m0 * N + n0) = v0;
                *(float2*)(out + (size_t)(m0 + 8) * N + n0) = v1;
            }
        }
    }
}

// ---------------------------------------------------------------------------
// Flash attention (unchanged): fp32 SIMT, BQ=BK=64, 256 threads.
// ---------------------------------------------------------------------------
__global__ __launch_bounds__(256) void attn_kernel()
{
    __shared__ float Qs[64][64];
    __shared__ float KP[64 * 64];
    __shared__ float Vs[64][64];

    const int tid = threadIdx.x;
    const int ty = tid >> 4;
    const int tx = tid & 15;
    const int qb = blockIdx.x;
    const int bh = blockIdx.y;
    const int q0 = qb * 64;
    const int ty4 = ty * 4;

    const size_t plane = (size_t)B_ * H_ * T_ * D_;
    const float* qbase = g_qkv + ((size_t)bh * T_ + q0) * D_;
    const float* kbase = g_qkv + plane + (size_t)bh * T_ * D_;
    const float* vbase = kbase + plane;

#pragma unroll
    for (int it = 0; it < 4; ++it) {
        int f = tid + it * 256;
        ((float4*)Qs)[f] = ((const float4*)qbase)[f];
    }

    float rO[4][4] = {};
    float mrow[4], lrow[4];
#pragma unroll
    for (int i = 0; i < 4; ++i) { mrow[i] = -1e30f; lrow[i] = 0.f; }

    for (int kb = 0; kb <= qb; ++kb) {
        const float4* ksrc = (const float4*)(kbase + (size_t)kb * 64 * D_);
        const float4* vsrc = (const float4*)(vbase + (size_t)kb * 64 * D_);
#pragma unroll
        for (int it = 0; it < 4; ++it) {
            int f = tid + it * 256;
            int r = f >> 4, c4 = f & 15;
            float4 kv = ksrc[f];
            int p4 = (c4 ^ (r >> 2)) & 15;
            *(float4*)&KP[r * 64 + p4 * 4] = kv;
            ((float4*)Vs)[f] = vsrc[f];
        }
        __syncthreads();

        float s[4][4] = {};
#pragma unroll 4
        for (int d4 = 0; d4 < 16; ++d4) {
            float av[4][4], bm[4][4];
            int p4 = (d4 ^ tx) & 15;
#pragma unroll
            for (int i = 0; i < 4; ++i)
                *(float4*)&av[i][0] = *(const float4*)&Qs[ty4 + i][d4 << 2];
#pragma unroll
            for (int j = 0; j < 4; ++j)
                *(float4*)&bm[j][0] = *(const float4*)&KP[(tx * 4 + j) * 64 + p4 * 4];
#pragma unroll
            for (int i = 0; i < 4; ++i)
#pragma unroll
                for (int j = 0; j < 4; ++j)
#pragma unroll
                    for (int u = 0; u < 4; ++u)
                        s[i][j] = fmaf(av[i][u], bm[j][u], s[i][j]);
        }

        const bool diag = (kb == qb);
#pragma unroll
        for (int i = 0; i < 4; ++i)
#pragma unroll
            for (int j = 0; j < 4; ++j) {
                float v = s[i][j] * 0.125f;
                if (diag && (tx * 4 + j) > (ty4 + i)) v = -1e30f;
                s[i][j] = v;
            }

#pragma unroll
        for (int i = 0; i < 4; ++i) {
            float mt = fmaxf(fmaxf(s[i][0], s[i][1]), fmaxf(s[i][2], s[i][3]));
#pragma unroll
            for (int w = 8; w >= 1; w >>= 1)
                mt = fmaxf(mt, __shfl_xor_sync(0xffffffffu, mt, w));
            float mn = fmaxf(mrow[i], mt);
            float alpha = __expf(mrow[i] - mn);
            mrow[i] = mn;
            float rs = 0.f;
#pragma unroll
            for (int j = 0; j < 4; ++j) {
                s[i][j] = __expf(s[i][j] - mn);
                rs += s[i][j];
            }
#pragma unroll
            for (int w = 8; w >= 1; w >>= 1)
                rs += __shfl_xor_sync(0xffffffffu, rs, w);
            lrow[i] = lrow[i] * alpha + rs;
#pragma unroll
            for (int j = 0; j < 4; ++j) rO[i][j] *= alpha;
        }

        __syncthreads();
#pragma unroll
        for (int i = 0; i < 4; ++i)
#pragma unroll
            for (int j = 0; j < 4; ++j)
                KP[(ty4 + i) * 64 + tx * 4 + j] = s[i][j];
        __syncthreads();

#pragma unroll 4
        for (int c4 = 0; c4 < 16; ++c4) {
            float av[4][4], bm[4][4];
#pragma unroll
            for (int i = 0; i < 4; ++i)
                *(float4*)&av[i][0] = *(const float4*)&KP[(ty4 + i) * 64 + (c4 << 2)];
#pragma unroll
            for (int u = 0; u < 4; ++u)
                *(float4*)&bm[u][0] = *(const float4*)&Vs[(c4 << 2) + u][tx * 4];
#pragma unroll
            for (int i = 0; i < 4; ++i)
#pragma unroll
                for (int u = 0; u < 4; ++u)
#pragma unroll
                    for (int j = 0; j < 4; ++j)
                        rO[i][j] = fmaf(av[i][u], bm[u][j], rO[i][j]);
        }
        __syncthreads();
    }

    const int b = bh >> 4, h = bh & 15;
    float* obase = g_att + (size_t)(b * T_ + q0) * C_ + h * D_;
#pragma unroll
    for (int i = 0; i < 4; ++i) {
        float inv = 1.0f / lrow[i];
        float4 o;
        o.x = rO[i][0] * inv; o.y = rO[i][1] * inv;
        o.z = rO[i][2] * inv; o.w = rO[i][3] * inv;
        *(float4*)(obase + (size_t)(ty4 + i) * C_ + tx * 4) = o;
    }
}

// ---------------------------------------------------------------------------
extern "C" void kernel_launch(void* const* d_in, const int* in_sizes, int n_in,
                              void* d_out, int out_size)
{
    const float* x      = (const float*)d_in[0];
    const float* w_qkv  = (const float*)d_in[1];
    const float* b_qkv  = (const float*)d_in[2];
    const float* w_proj = (const float*)d_in[3];
    const float* b_proj = (const float*)d_in[4];
    float* out = (float*)d_out;

    // 1) QKV projection (HMMA bf16x3)
    gemm_mma<0><<<dim3((3 * C_) / 128, (B_ * T_) / 128), 256>>>(
        x, w_qkv, b_qkv, nullptr, B_ * T_, 3 * C_, C_);

    // 2) causal flash attention -> g_att [B,T,C]
    attn_kernel<<<dim3(T_ / 64, B_ * H_), 256>>>();

    // 3) output projection (HMMA bf16x3)
    gemm_mma<1><<<dim3(C_ / 128, (B_ * T_) / 128), 256>>>(
        nullptr, w_proj, b_proj, out, B_ * T_, C_, C_);
}

// round 7
// speedup vs baseline: 2.5996x; 1.6065x over previous
#include <cuda_runtime.h>
#include <cuda_bf16.h>
#include <cstdint>

#define B_ 4
#define T_ 2048
#define C_ 1024
#define H_ 16
#define D_ 64

// Scratch (static __device__ globals: allocation-free per harness rules)
__device__ float g_qkv[(size_t)3 * B_ * H_ * T_ * D_];   // [which][b][h][t][d]
__device__ float g_att[(size_t)B_ * T_ * C_];            // [b][t][h*D+d]

// ---------------------------------------------------------------------------
// Helpers (compute_103-safe: only ldmatrix + mma.sync, no tcgen05)
// ---------------------------------------------------------------------------
static __device__ __forceinline__ uint32_t smem_u32(const void* p) {
    uint32_t a;
    asm("{ .reg .u64 t; cvta.to.shared.u64 t, %1; cvt.u32.u64 %0, t; }"
        : "=r"(a) : "l"(p));
    return a;
}

#define LDM_X4(r, addr) \
    asm volatile("ldmatrix.sync.aligned.m8n8.x4.shared.b16 {%0,%1,%2,%3}, [%4];" \
        : "=r"((r)[0]), "=r"((r)[1]), "=r"((r)[2]), "=r"((r)[3]) : "r"(addr))

#define LDM_X4T(r, addr) \
    asm volatile("ldmatrix.sync.aligned.m8n8.x4.trans.shared.b16 {%0,%1,%2,%3}, [%4];" \
        : "=r"((r)[0]), "=r"((r)[1]), "=r"((r)[2]), "=r"((r)[3]) : "r"(addr))

#define MMA_BF16(d, a, b0, b1) \
    asm volatile("mma.sync.aligned.m16n8k16.row.col.f32.bf16.bf16.f32 " \
        "{%0,%1,%2,%3}, {%4,%5,%6,%7}, {%8,%9}, {%0,%1,%2,%3};" \
        : "+f"((d)[0]), "+f"((d)[1]), "+f"((d)[2]), "+f"((d)[3]) \
        : "r"((a)[0]), "r"((a)[1]), "r"((a)[2]), "r"((a)[3]), "r"(b0), "r"(b1))

// fp32 -> (hi, lo) bf16 split
static __device__ __forceinline__ void split2(float v, __nv_bfloat16& h, __nv_bfloat16& l) {
    h = __float2bfloat16_rn(v);
    l = __float2bfloat16_rn(v - __bfloat162float(h));
}
static __device__ __forceinline__ uint32_t pack2(__nv_bfloat16 a, __nv_bfloat16 b) {
    __nv_bfloat162 t; t.x = a; t.y = b;
    uint32_t u; __builtin_memcpy(&u, &t, 4);
    return u;
}
static __device__ __forceinline__ uint32_t pack2f(float a, float b) {
    __nv_bfloat162 t; t.x = __float2bfloat16_rn(a); t.y = __float2bfloat16_rn(b);
    uint32_t u; __builtin_memcpy(&u, &t, 4);
    return u;
}

// Padded strides (elements): A rows 40 bf16 (80B), B rows 136 bf16 (272B).
// 80*i mod 128 and 272*i mod 128 both cycle through 8 distinct 16B banks ->
// conflict-free ldmatrix.
#define A_PITCH 40
#define B_PITCH 136

// ---------------------------------------------------------------------------
// HMMA GEMM with bf16x3 split (unchanged from round 5): out = A @ W + bias
// ---------------------------------------------------------------------------
template <int MODE>
__global__ __launch_bounds__(256, 2) void gemm_mma(
    const float* __restrict__ A, const float* __restrict__ W,
    const float* __restrict__ bias, float* __restrict__ out,
    int M, int N, int K)
{
    __shared__ __align__(16) __nv_bfloat16 AsH[128 * A_PITCH];
    __shared__ __align__(16) __nv_bfloat16 AsL[128 * A_PITCH];
    __shared__ __align__(16) __nv_bfloat16 BsH[32 * B_PITCH];
    __shared__ __align__(16) __nv_bfloat16 BsL[32 * B_PITCH];

    const int tid = threadIdx.x;
    const int wid = tid >> 5;
    const int lane = tid & 31;
    const int wm = wid >> 1;
    const int wn = wid & 1;
    const int bm = blockIdx.y, bn = blockIdx.x;

    const uint32_t sAH = smem_u32(AsH), sAL = smem_u32(AsL);
    const uint32_t sBH = smem_u32(BsH), sBL = smem_u32(BsL);

    const float* Aeff = (MODE == 1) ? g_att : A;
    const float* Ap = Aeff + (size_t)bm * 128 * K;
    const float* Wp = W + (size_t)bn * 128;

    float acc[2][8][4] = {};

    const int l15 = lane & 15;
    const int lhi = lane >> 4;
    const uint32_t a_off0 = (uint32_t)(wm * 32 + l15) * (A_PITCH * 2) + (lhi << 4);
    const uint32_t b_off0 = (uint32_t)l15 * (B_PITCH * 2) + ((wn * 64 + (lhi << 3)) << 1);

    for (int kt = 0; kt < K / 32; ++kt) {
#pragma unroll
        for (int i = 0; i < 4; ++i) {
            int f = tid + i * 256;
            {
                int r = f >> 3, c4 = f & 7;
                float4 v = *(const float4*)(Ap + (size_t)r * K + kt * 32 + c4 * 4);
                __nv_bfloat16 h0, h1, h2, h3, l0, l1, l2, l3;
                split2(v.x, h0, l0); split2(v.y, h1, l1);
                split2(v.z, h2, l2); split2(v.w, h3, l3);
                int e = r * A_PITCH + c4 * 4;
                *(uint2*)&AsH[e] = make_uint2(pack2(h0, h1), pack2(h2, h3));
                *(uint2*)&AsL[e] = make_uint2(pack2(l0, l1), pack2(l2, l3));
            }
            {
                int r = f >> 5, c4 = f & 31;
                float4 v = *(const float4*)(Wp + (size_t)(kt * 32 + r) * N + c4 * 4);
                __nv_bfloat16 h0, h1, h2, h3, l0, l1, l2, l3;
                split2(v.x, h0, l0); split2(v.y, h1, l1);
                split2(v.z, h2, l2); split2(v.w, h3, l3);
                int e = r * B_PITCH + c4 * 4;
                *(uint2*)&BsH[e] = make_uint2(pack2(h0, h1), pack2(h2, h3));
                *(uint2*)&BsL[e] = make_uint2(pack2(l0, l1), pack2(l2, l3));
            }
        }
        __syncthreads();

#pragma unroll
        for (int ks = 0; ks < 2; ++ks) {
            uint32_t ah[2][4], al[2][4], bfr[4][4];
#pragma unroll
            for (int mf = 0; mf < 2; ++mf) {
                uint32_t ao = a_off0 + (uint32_t)mf * 16 * (A_PITCH * 2) + ks * 32;
                LDM_X4(ah[mf], sAH + ao);
                LDM_X4(al[mf], sAL + ao);
            }
            const uint32_t bks = b_off0 + (uint32_t)ks * 16 * (B_PITCH * 2);
#pragma unroll
            for (int ng = 0; ng < 4; ++ng)
                LDM_X4T(bfr[ng], sBH + bks + ng * 32);
#pragma unroll
            for (int mf = 0; mf < 2; ++mf)
#pragma unroll
                for (int nf = 0; nf < 8; ++nf)
                    MMA_BF16(acc[mf][nf], ah[mf], bfr[nf >> 1][(nf & 1) * 2],
                             bfr[nf >> 1][(nf & 1) * 2 + 1]);
#pragma unroll
            for (int mf = 0; mf < 2; ++mf)
#pragma unroll
                for (int nf = 0; nf < 8; ++nf)
                    MMA_BF16(acc[mf][nf], al[mf], bfr[nf >> 1][(nf & 1) * 2],
                             bfr[nf >> 1][(nf & 1) * 2 + 1]);
#pragma unroll
            for (int ng = 0; ng < 4; ++ng)
                LDM_X4T(bfr[ng], sBL + bks + ng * 32);
#pragma unroll
            for (int mf = 0; mf < 2; ++mf)
#pragma unroll
                for (int nf = 0; nf < 8; ++nf)
                    MMA_BF16(acc[mf][nf], ah[mf], bfr[nf >> 1][(nf & 1) * 2],
                             bfr[nf >> 1][(nf & 1) * 2 + 1]);
        }
        __syncthreads();
    }

    const int tr = lane >> 2;
    const int tc = (lane & 3) * 2;
#pragma unroll
    for (int mf = 0; mf < 2; ++mf) {
        const int m0 = bm * 128 + wm * 32 + mf * 16 + tr;
#pragma unroll
        for (int nf = 0; nf < 8; ++nf) {
            const int n0 = bn * 128 + wn * 64 + nf * 8 + tc;
            const float bx = __ldg(&bias[n0]);
            const float by = __ldg(&bias[n0 + 1]);
            float2 v0 = make_float2(acc[mf][nf][0] + bx, acc[mf][nf][1] + by);
            float2 v1 = make_float2(acc[mf][nf][2] + bx, acc[mf][nf][3] + by);
            if (MODE == 0) {
                const int which = n0 >> 10;
                const int h = (n0 & 1023) >> 6;
                const int d0 = n0 & 63;
                {
                    int bb = m0 >> 11, t = m0 & 2047;
                    *(float2*)&g_qkv[(((((size_t)which * B_ + bb) * H_ + h) * T_ + t) * D_) + d0] = v0;
                }
                {
                    int m1 = m0 + 8;
                    int bb = m1 >> 11, t = m1 & 2047;
                    *(float2*)&g_qkv[(((((size_t)which * B_ + bb) * H_ + h) * T_ + t) * D_) + d0] = v1;
                }
            } else {
                *(float2*)(out + (size_t)m0 * N + n0) = v0;
                *(float2*)(out + (size_t)(m0 + 8) * N + n0) = v1;
            }
        }
    }
}

// ---------------------------------------------------------------------------
// HMMA flash attention, causal, bf16x3 split for both Q@K^T and P@V.
// BQ=128 per CTA, BK=64. 256 threads = 8 warps; warp w owns q-rows
// [w*16, w*16+16) and the full key/d width -> softmax is warp-local.
// K tile [key][d] is exactly the B[n][k] layout for row.col mma (non-trans
// ldmatrix); V needs trans ldmatrix. P is rebuilt from S acc frags entirely
// in registers (acc m16n8 pair -> A m16k16 frag).
// ---------------------------------------------------------------------------
#define AT_PITCH 72   // 144B rows: 16*i mod 128 cycles all 8 bank columns

__global__ __launch_bounds__(256, 2) void attn_mma()
{
    __shared__ __align__(16) __nv_bfloat16 KHs[64 * AT_PITCH];
    __shared__ __align__(16) __nv_bfloat16 KLs[64 * AT_PITCH];
    __shared__ __align__(16) __nv_bfloat16 VHs[64 * AT_PITCH];
    __shared__ __align__(16) __nv_bfloat16 VLs[64 * AT_PITCH];

    const int tid = threadIdx.x;
    const int wid = tid >> 5;
    const int lane = tid & 31;
    const int l15 = lane & 15;
    const int lhi = lane >> 4;
    const int tr = lane >> 2;
    const int tc = (lane & 3) * 2;

    const int qb = blockIdx.x;
    const int bh = blockIdx.y;
    const int q0 = qb * 128;

    const uint32_t sKH = smem_u32(KHs), sKL = smem_u32(KLs);
    const uint32_t sVH = smem_u32(VHs), sVL = smem_u32(VLs);

    const size_t plane = (size_t)B_ * H_ * T_ * D_;
    const float* qbase = g_qkv + ((size_t)bh * T_ + q0) * D_;
    const float* kbase = g_qkv + plane + (size_t)bh * T_ * D_;
    const float* vbase = kbase + plane;

    // ---- Q tile -> registers (hi/lo A-frags), staged through KH/KL in halves
    uint32_t qh[4][4], ql[4][4];
#pragma unroll
    for (int half = 0; half < 2; ++half) {
#pragma unroll
        for (int i = 0; i < 4; ++i) {
            int f = tid + i * 256;
            int r = f >> 4, c4 = f & 15;
            float4 v = *(const float4*)(qbase + (size_t)(half * 64 + r) * D_ + c4 * 4);
            __nv_bfloat16 h0, h1, h2, h3, l0, l1, l2, l3;
            split2(v.x, h0, l0); split2(v.y, h1, l1);
            split2(v.z, h2, l2); split2(v.w, h3, l3);
            int e = r * AT_PITCH + c4 * 4;
            *(uint2*)&KHs[e] = make_uint2(pack2(h0, h1), pack2(h2, h3));
            *(uint2*)&KLs[e] = make_uint2(pack2(l0, l1), pack2(l2, l3));
        }
        __syncthreads();
        if ((wid >> 2) == half) {
            const uint32_t qoff =
                (uint32_t)((wid & 3) * 16 + l15) * (AT_PITCH * 2) + (lhi << 4);
#pragma unroll
            for (int s = 0; s < 4; ++s) {
                LDM_X4(qh[s], sKH + qoff + s * 32);
                LDM_X4(ql[s], sKL + qoff + s * 32);
            }
        }
        __syncthreads();
    }

    float o[8][4] = {};
    float m0 = -1e30f, m1 = -1e30f, lsum0 = 0.f, lsum1 = 0.f;

    const int row0 = q0 + wid * 16 + tr;       // this thread's two q-rows
    const int row1 = row0 + 8;
    const int warp_qhi = q0 + wid * 16 + 15;
    const int ktiles = 2 * qb + 2;

    for (int kb = 0; kb < ktiles; ++kb) {
        __syncthreads();   // previous tile's compute fully done
        // ---- load K,V 64x64 fp32 -> hi/lo bf16 tiles
        const float4* ksrc = (const float4*)(kbase + (size_t)kb * 64 * D_);
        const float4* vsrc = (const float4*)(vbase + (size_t)kb * 64 * D_);
#pragma unroll
        for (int i = 0; i < 4; ++i) {
            int f = tid + i * 256;
            int r = f >> 4, c4 = f & 15;
            int e = r * AT_PITCH + c4 * 4;
            {
                float4 v = ksrc[f];
                __nv_bfloat16 h0, h1, h2, h3, l0, l1, l2, l3;
                split2(v.x, h0, l0); split2(v.y, h1, l1);
                split2(v.z, h2, l2); split2(v.w, h3, l3);
                *(uint2*)&KHs[e] = make_uint2(pack2(h0, h1), pack2(h2, h3));
                *(uint2*)&KLs[e] = make_uint2(pack2(l0, l1), pack2(l2, l3));
            }
            {
                float4 v = vsrc[f];
                __nv_bfloat16 h0, h1, h2, h3, l0, l1, l2, l3;
                split2(v.x, h0, l0); split2(v.y, h1, l1);
                split2(v.z, h2, l2); split2(v.w, h3, l3);
                *(uint2*)&VHs[e] = make_uint2(pack2(h0, h1), pack2(h2, h3));
                *(uint2*)&VLs[e] = make_uint2(pack2(l0, l1), pack2(l2, l3));
            }
        }
        __syncthreads();

        if (kb * 64 > warp_qhi) continue;      // fully masked for this warp

        // ---- S = Q @ K^T (bf16x3)
        float s[8][4] = {};
#pragma unroll
        for (int ks = 0; ks < 4; ++ks)
#pragma unroll
            for (int ng = 0; ng < 4; ++ng) {
                uint32_t bh4[4], bl4[4];
                const uint32_t ka =
                    (uint32_t)(ng * 16 + l15) * (AT_PITCH * 2) + ks * 32 + (lhi << 4);
                LDM_X4(bh4, sKH + ka);
                LDM_X4(bl4, sKL + ka);
                MMA_BF16(s[2 * ng],     qh[ks], bh4[0], bh4[2]);
                MMA_BF16(s[2 * ng + 1], qh[ks], bh4[1], bh4[3]);
                MMA_BF16(s[2 * ng],     qh[ks], bl4[0], bl4[2]);
                MMA_BF16(s[2 * ng + 1], qh[ks], bl4[1], bl4[3]);
                MMA_BF16(s[2 * ng],     ql[ks], bh4[0], bh4[2]);
                MMA_BF16(s[2 * ng + 1], ql[ks], bh4[1], bh4[3]);
            }

        // ---- scale + causal mask (only tiles touching the diagonal)
        const bool diag = (kb >= 2 * qb);
#pragma unroll
        for (int nf = 0; nf < 8; ++nf) {
            const int c0 = kb * 64 + nf * 8 + tc;
            s[nf][0] *= 0.125f; s[nf][1] *= 0.125f;
            s[nf][2] *= 0.125f; s[nf][3] *= 0.125f;
            if (diag) {
                if (c0 > row0)     s[nf][0] = -1e30f;
                if (c0 + 1 > row0) s[nf][1] = -1e30f;
                if (c0 > row1)     s[nf][2] = -1e30f;
                if (c0 + 1 > row1) s[nf][3] = -1e30f;
            }
        }

        // ---- online softmax (rows tr / tr+8; reduce over lane^1, lane^2)
        float mt0 = -1e30f, mt1 = -1e30f;
#pragma unroll
        for (int nf = 0; nf < 8; ++nf) {
            mt0 = fmaxf(mt0, fmaxf(s[nf][0], s[nf][1]));
            mt1 = fmaxf(mt1, fmaxf(s[nf][2], s[nf][3]));
        }
        mt0 = fmaxf(mt0, __shfl_xor_sync(0xffffffffu, mt0, 1));
        mt0 = fmaxf(mt0, __shfl_xor_sync(0xffffffffu, mt0, 2));
        mt1 = fmaxf(mt1, __shfl_xor_sync(0xffffffffu, mt1, 1));
        mt1 = fmaxf(mt1, __shfl_xor_sync(0xffffffffu, mt1, 2));
        const float mn0 = fmaxf(m0, mt0), mn1 = fmaxf(m1, mt1);
        const float al0 = __expf(m0 - mn0), al1 = __expf(m1 - mn1);
        m0 = mn0; m1 = mn1;

        float rs0 = 0.f, rs1 = 0.f;
#pragma unroll
        for (int nf = 0; nf < 8; ++nf) {
            s[nf][0] = __expf(s[nf][0] - mn0);
            s[nf][1] = __expf(s[nf][1] - mn0);
            s[nf][2] = __expf(s[nf][2] - mn1);
            s[nf][3] = __expf(s[nf][3] - mn1);
            rs0 += s[nf][0] + s[nf][1];
            rs1 += s[nf][2] + s[nf][3];
        }
        rs0 += __shfl_xor_sync(0xffffffffu, rs0, 1);
        rs0 += __shfl_xor_sync(0xffffffffu, rs0, 2);
        rs1 += __shfl_xor_sync(0xffffffffu, rs1, 1);
        rs1 += __shfl_xor_sync(0xffffffffu, rs1, 2);
        lsum0 = lsum0 * al0 + rs0;
        lsum1 = lsum1 * al1 + rs1;
#pragma unroll
        for (int nf = 0; nf < 8; ++nf) {
            o[nf][0] *= al0; o[nf][1] *= al0;
            o[nf][2] *= al1; o[nf][3] *= al1;
        }

        // ---- O += P @ V (bf16x3; P frags built in registers from S)
#pragma unroll
        for (int ks = 0; ks < 4; ++ks) {
            uint32_t ah[4], alo[4];
            {
                const float* p0 = s[2 * ks];
                const float* p1 = s[2 * ks + 1];
                float hv[8], lv[8];
                const float pv[8] = {p0[0], p0[1], p0[2], p0[3],
                                     p1[0], p1[1], p1[2], p1[3]};
#pragma unroll
                for (int e = 0; e < 8; ++e) {
                    __nv_bfloat16 hh, ll;
                    split2(pv[e], hh, ll);
                    hv[e] = __bfloat162float(hh);
                    lv[e] = pv[e] - hv[e];
                }
                ah[0] = pack2f(hv[0], hv[1]); ah[1] = pack2f(hv[2], hv[3]);
                ah[2] = pack2f(hv[4], hv[5]); ah[3] = pack2f(hv[6], hv[7]);
                alo[0] = pack2f(lv[0], lv[1]); alo[1] = pack2f(lv[2], lv[3]);
                alo[2] = pack2f(lv[4], lv[5]); alo[3] = pack2f(lv[6], lv[7]);
            }
#pragma unroll
            for (int ng = 0; ng < 4; ++ng) {
                uint32_t vh4[4], vl4[4];
                const uint32_t va =
                    (uint32_t)(ks * 16 + l15) * (AT_PITCH * 2) + ((ng * 16 + lhi * 8) << 1);
                LDM_X4T(vh4, sVH + va);
                LDM_X4T(vl4, sVL + va);
                MMA_BF16(o[2 * ng],     ah,  vh4[0], vh4[1]);
                MMA_BF16(o[2 * ng + 1], ah,  vh4[2], vh4[3]);
                MMA_BF16(o[2 * ng],     ah,  vl4[0], vl4[1]);
                MMA_BF16(o[2 * ng + 1], ah,  vl4[2], vl4[3]);
                MMA_BF16(o[2 * ng],     alo, vh4[0], vh4[1]);
                MMA_BF16(o[2 * ng + 1], alo, vh4[2], vh4[3]);
            }
        }
    }

    // ---- normalize + write to g_att [B, T, H*D]
    const int b = bh >> 4, h = bh & 15;
    const float inv0 = 1.0f / lsum0;
    const float inv1 = 1.0f / lsum1;
    float* ob0 = g_att + ((size_t)(b * T_ + row0) * C_) + h * D_;
    float* ob1 = g_att + ((size_t)(b * T_ + row1) * C_) + h * D_;
#pragma unroll
    for (int nf = 0; nf < 8; ++nf) {
        const int d = nf * 8 + tc;
        *(float2*)(ob0 + d) = make_float2(o[nf][0] * inv0, o[nf][1] * inv0);
        *(float2*)(ob1 + d) = make_float2(o[nf][2] * inv1, o[nf][3] * inv1);
    }
}

// ---------------------------------------------------------------------------
extern "C" void kernel_launch(void* const* d_in, const int* in_sizes, int n_in,
                              void* d_out, int out_size)
{
    const float* x      = (const float*)d_in[0];
    const float* w_qkv  = (const float*)d_in[1];
    const float* b_qkv  = (const float*)d_in[2];
    const float* w_proj = (const float*)d_in[3];
    const float* b_proj = (const float*)d_in[4];
    float* out = (float*)d_out;

    // 1) QKV projection (HMMA bf16x3)
    gemm_mma<0><<<dim3((3 * C_) / 128, (B_ * T_) / 128), 256>>>(
        x, w_qkv, b_qkv, nullptr, B_ * T_, 3 * C_, C_);

    // 2) causal flash attention (HMMA bf16x3) -> g_att [B,T,C]
    attn_mma<<<dim3(T_ / 128, B_ * H_), 256>>>();

    // 3) output projection (HMMA bf16x3)
    gemm_mma<1><<<dim3(C_ / 128, (B_ * T_) / 128), 256>>>(
        nullptr, w_proj, b_proj, out, B_ * T_, C_, C_);
}